// round 6
// baseline (speedup 1.0000x reference)
#include <cuda_runtime.h>
#include <cstddef>

#define N_NODES 4096
#define BB 2
#define TT 5
#define DD 4
#define FF 64
#define HH 64
#define EE 3
#define PSTEPS 10
#define BN (BB*N_NODES)   /* 8192 */
#define NH (N_NODES*HH)   /* 262144 */

// Scratch (no allocation allowed -> __device__ globals)
__device__ float g_window[BB*N_NODES*TT*DD];      // [B][N][T][D]
__device__ float g_cond[BN*FF];                   // [B*N][F]
__device__ float g_Z[EE*BB*NH];                   // [E][B][N][H]  (cond @ W1_e)
__device__ float g_pre[EE*BB*NH];                 // [E][B][N][H]  (cond @ W2_e + b_e)
__device__ float g_part[2*EE*BB*NH];              // [S=2][E][B][N][H] K-split partials
__device__ float g_mask[N_NODES];

// ---------------------------------------------------------------------------
// Window init: time_segs [B,T,N,D] -> window [B,N,T,D]
__global__ void k_init_window(const float* __restrict__ ts) {
    int idx = blockIdx.x * 256 + threadIdx.x;     // grid covers exactly 163840
    int d = idx & 3;
    int r = idx >> 2;
    int t = r % TT;
    int bn = r / TT;
    int n = bn & (N_NODES - 1);
    int b = bn >> 12;
    g_window[idx] = ts[(((size_t)(b*TT + t))*N_NODES + n)*DD + d];
}

// node_mask[m] = any over (e,n) of adjs[e][n][m] > 0  (entries are >= 0)
__global__ void k_mask(const float* __restrict__ adjs) {
    int m = blockIdx.x * 256 + threadIdx.x;
    float v = 0.f;
    for (size_t i = m; i < (size_t)EE*N_NODES*N_NODES; i += N_NODES) {
        if (adjs[i] > 0.f) { v = 1.f; break; }
    }
    g_mask[m] = v;
}

// ---------------------------------------------------------------------------
// cond[b,n,f] = sum_{t,d} window[b,n,t,d] * conv_w[t,d,f] + conv_b[f]
__global__ void k_conv(const float* __restrict__ cw, const float* __restrict__ cb) {
    int idx = blockIdx.x * 256 + threadIdx.x;     // grid 2048 -> 524288 = BN*FF
    int f = idx & 63;
    int g = idx >> 6;
    const float* w = g_window + (size_t)g * (TT*DD);
    float acc = cb[f];
#pragma unroll
    for (int td = 0; td < TT*DD; td++)
        acc = fmaf(w[td], cw[td*FF + f], acc);
    g_cond[idx] = acc;
}

// ---------------------------------------------------------------------------
// Small GEMM: Z[e] = cond @ enc_w1[e], pre[e] = cond @ enc_w2[e] + enc_b[e]
// grid: (128 row-tiles of 64, 6) y<3 -> W1->Z, y>=3 -> W2->pre
__global__ __launch_bounds__(256) void k_zpre(const float* __restrict__ w1,
                                              const float* __restrict__ w2,
                                              const float* __restrict__ encb) {
    __shared__ float CsT[64][68];   // [k][row]
    __shared__ float Ws[64][64];    // [k][col]
    int tid = threadIdx.x;
    int y = blockIdx.y;
    int e = (y < 3) ? y : y - 3;
    const float* W = ((y < 3) ? w1 : w2) + e*FF*HH;
    int r0 = blockIdx.x * 64;

#pragma unroll
    for (int l = 0; l < 4; l++) {
        int q = tid + l*256;            // 0..1023 float4s
        int r = q >> 4, kq = q & 15;
        float4 v = *(const float4*)(g_cond + (size_t)(r0 + r)*64 + kq*4);
        CsT[kq*4+0][r] = v.x; CsT[kq*4+1][r] = v.y;
        CsT[kq*4+2][r] = v.z; CsT[kq*4+3][r] = v.w;
        *(float4*)&Ws[r][kq*4] = *(const float4*)(W + r*64 + kq*4);
    }
    __syncthreads();

    int tx = tid & 15, ty = tid >> 4;
    float acc[4][4] = {};
#pragma unroll 16
    for (int k = 0; k < 64; k++) {
        float4 a  = *(float4*)&CsT[k][ty*4];
        float4 bv = *(float4*)&Ws[k][tx*4];
        float av[4] = {a.x, a.y, a.z, a.w};
        float bb[4] = {bv.x, bv.y, bv.z, bv.w};
#pragma unroll
        for (int i = 0; i < 4; i++)
#pragma unroll
            for (int j = 0; j < 4; j++)
                acc[i][j] = fmaf(av[i], bb[j], acc[i][j]);
    }

    float* out = ((y < 3) ? g_Z : g_pre) + (size_t)e * (BN*HH);
    float b0 = 0.f, b1 = 0.f, b2 = 0.f, b3 = 0.f;
    if (y >= 3) {
        b0 = encb[e*64 + tx*4 + 0]; b1 = encb[e*64 + tx*4 + 1];
        b2 = encb[e*64 + tx*4 + 2]; b3 = encb[e*64 + tx*4 + 3];
    }
#pragma unroll
    for (int i = 0; i < 4; i++) {
        float4 v = make_float4(acc[i][0]+b0, acc[i][1]+b1, acc[i][2]+b2, acc[i][3]+b3);
        *(float4*)(out + (size_t)(r0 + ty*4 + i)*64 + tx*4) = v;
    }
}

// ---------------------------------------------------------------------------
// Big GEMM with K-split: part[s,e,b,n,h] = sum_{m in Kslice(s)} A_e[n,m]*Z[e,b,m,h]
// Block: 64 rows x 128 cols (2 batches x 64h), 256 threads, micro 4x8, KT=32.
// grid (64 row-tiles, E=3, S=2) = 384 blocks.
__global__ __launch_bounds__(256, 3) void k_big(const float* __restrict__ adjs) {
    __shared__ float As[32][68];        // [k][row]
    __shared__ float Zs[2][32][64];     // [b][k][h]
    int tid = threadIdx.x;
    int e = blockIdx.y, s = blockIdx.z;
    int n0 = blockIdx.x * 64;
    int k0 = s * 2048;
    const float* A  = adjs + (size_t)e * N_NODES * N_NODES;
    const float* Z0 = g_Z + (size_t)(e*2 + 0) * NH;
    const float* Z1 = g_Z + (size_t)(e*2 + 1) * NH;

    int tx = tid & 15, ty = tid >> 4;
    int colb = tx >> 3;
    int colh = (tx & 7) * 8;
    float acc[4][8] = {};

    int qa = tid * 2;
    int ar0 = qa >> 3,       akq0 = qa & 7;
    int ar1 = (qa+1) >> 3,   akq1 = (qa+1) & 7;
    int zr0 = qa >> 4,       zh0 = (qa & 15) * 4;
    int zr1 = (qa+1) >> 4,   zh1 = ((qa+1) & 15) * 4;
    float4 ra0, ra1, rz00, rz01, rz10, rz11;

#define LOADT(kk) do { \
    ra0  = *(const float4*)(A + (size_t)(n0+ar0)*N_NODES + (kk) + akq0*4); \
    ra1  = *(const float4*)(A + (size_t)(n0+ar1)*N_NODES + (kk) + akq1*4); \
    rz00 = *(const float4*)(Z0 + (size_t)((kk)+zr0)*64 + zh0); \
    rz01 = *(const float4*)(Z0 + (size_t)((kk)+zr1)*64 + zh1); \
    rz10 = *(const float4*)(Z1 + (size_t)((kk)+zr0)*64 + zh0); \
    rz11 = *(const float4*)(Z1 + (size_t)((kk)+zr1)*64 + zh1); \
} while (0)

#define STORET() do { \
    As[akq0*4+0][ar0]=ra0.x; As[akq0*4+1][ar0]=ra0.y; As[akq0*4+2][ar0]=ra0.z; As[akq0*4+3][ar0]=ra0.w; \
    As[akq1*4+0][ar1]=ra1.x; As[akq1*4+1][ar1]=ra1.y; As[akq1*4+2][ar1]=ra1.z; As[akq1*4+3][ar1]=ra1.w; \
    *(float4*)&Zs[0][zr0][zh0] = rz00; *(float4*)&Zs[0][zr1][zh1] = rz01; \
    *(float4*)&Zs[1][zr0][zh0] = rz10; *(float4*)&Zs[1][zr1][zh1] = rz11; \
} while (0)

    LOADT(k0); STORET(); __syncthreads();
    for (int kt = 0; kt < 64; kt++) {
        if (kt + 1 < 64) LOADT(k0 + (kt+1)*32);
#pragma unroll 8
        for (int k = 0; k < 32; k++) {
            float4 a  = *(float4*)&As[k][ty*4];
            float4 z0 = *(float4*)&Zs[colb][k][colh];
            float4 z1 = *(float4*)&Zs[colb][k][colh+4];
            float av[4] = {a.x, a.y, a.z, a.w};
            float zv[8] = {z0.x, z0.y, z0.z, z0.w, z1.x, z1.y, z1.z, z1.w};
#pragma unroll
            for (int i = 0; i < 4; i++)
#pragma unroll
                for (int j = 0; j < 8; j++)
                    acc[i][j] = fmaf(av[i], zv[j], acc[i][j]);
        }
        __syncthreads();
        if (kt + 1 < 64) { STORET(); __syncthreads(); }
    }

    float* out = g_part + (((size_t)s*3 + e)*2 + colb) * NH;
#pragma unroll
    for (int i = 0; i < 4; i++) {
        size_t row = n0 + ty*4 + i;
        *(float4*)(out + row*64 + colh)     = make_float4(acc[i][0], acc[i][1], acc[i][2], acc[i][3]);
        *(float4*)(out + row*64 + colh + 4) = make_float4(acc[i][4], acc[i][5], acc[i][6], acc[i][7]);
    }
#undef LOADT
#undef STORET
}

// ---------------------------------------------------------------------------
// Combine + decoder + residual + window shift + write prediction slice.
// Block: 256 threads = 4 nodes x 64 lanes, 4 iterations -> 16 nodes/block.
__global__ __launch_bounds__(256) void k_decode(const float* __restrict__ dw,
                                                const float* __restrict__ db,
                                                const float* __restrict__ ow,
                                                const float* __restrict__ ob,
                                                float* __restrict__ outp, int step) {
    __shared__ float s_dw[64][132];   // transposed: [h][j], padded
    __shared__ float s_ow[64][4];
    __shared__ float s_db[64];
    __shared__ float s_ob[4];
    __shared__ float x[4][128];
    __shared__ float hv[4][64];
    __shared__ float nxt[4][4];
    int tid = threadIdx.x;

#pragma unroll
    for (int l = 0; l < 32; l++) {
        int q = tid + l*256;                 // dec_w linear: j*64 + h
        s_dw[q & 63][q >> 6] = dw[q];
    }
    s_ow[tid >> 2][tid & 3] = ow[tid];       // out_w: 64x4 = 256
    if (tid < 64) s_db[tid] = db[tid];
    if (tid < 4)  s_ob[tid] = ob[tid];
    __syncthreads();

    int ty = tid >> 6, tx = tid & 63;
    int base = blockIdx.x * 16;
    for (int i = 0; i < 4; i++) {
        int g = base + i*4 + ty;
        int b = g >> 12, n = g & (N_NODES - 1);

        // encoded = tanh(sum_e tanh(part0+part1+pre)) * mask
        float cv = g_cond[(size_t)g*64 + tx];
        float ssum = 0.f;
#pragma unroll
        for (int e = 0; e < 3; e++) {
            size_t o0 = (size_t)(e*2 + b) * NH + (size_t)n*64 + tx;
            float pe = g_part[o0] + g_part[(size_t)6*NH + o0] + g_pre[o0];
            ssum += tanhf(pe);
        }
        float enc = tanhf(ssum) * g_mask[n];
        x[ty][tx] = cv;
        x[ty][64 + tx] = enc;
        __syncthreads();

        // h = relu([cond, enc] @ dec_w + dec_b)
        float h = s_db[tx];
#pragma unroll
        for (int j = 0; j < 128; j += 4) {
            float4 xx = *(float4*)&x[ty][j];
            float4 ww = *(float4*)&s_dw[tx][j];
            h = fmaf(xx.x, ww.x, h); h = fmaf(xx.y, ww.y, h);
            h = fmaf(xx.z, ww.z, h); h = fmaf(xx.w, ww.w, h);
        }
        h = fmaxf(h, 0.f);
        hv[ty][tx] = h;
        __syncthreads();

        // nxt = win[:, -1, :] + tanh(h @ out_w + out_b); window shift
        float wv = 0.f;
        if (tx < 16) wv = g_window[((size_t)g*5 + 1 + (tx >> 2))*4 + (tx & 3)];
        if (tx < 4) {
            float o = s_ob[tx];
#pragma unroll
            for (int j = 0; j < 64; j++) o = fmaf(hv[ty][j], s_ow[j][tx], o);
            float nv = g_window[((size_t)g*5 + 4)*4 + tx] + tanhf(o);
            nxt[ty][tx] = nv;
            outp[(((size_t)b*PSTEPS + step)*N_NODES + n)*4 + tx] = nv;
        }
        __syncthreads();
        if (tx < 16)      g_window[((size_t)g*5 + (tx >> 2))*4 + (tx & 3)] = wv;
        else if (tx < 20) g_window[((size_t)g*5 + 4)*4 + (tx - 16)] = nxt[ty][tx - 16];
        __syncthreads();
    }
}

// ---------------------------------------------------------------------------
extern "C" void kernel_launch(void* const* d_in, const int* in_sizes, int n_in,
                              void* d_out, int out_size) {
    const float* ts   = (const float*)d_in[0];
    const float* adjs = (const float*)d_in[1];
    const float* cw   = (const float*)d_in[2];
    const float* cb   = (const float*)d_in[3];
    const float* w1   = (const float*)d_in[4];
    const float* w2   = (const float*)d_in[5];
    const float* encb = (const float*)d_in[6];
    const float* dw   = (const float*)d_in[7];
    const float* db   = (const float*)d_in[8];
    const float* ow   = (const float*)d_in[9];
    const float* ob   = (const float*)d_in[10];
    float* outp = (float*)d_out;

    k_init_window<<<640, 256>>>(ts);
    k_mask<<<16, 256>>>(adjs);
    for (int p = 0; p < PSTEPS; p++) {
        k_conv<<<2048, 256>>>(cw, cb);
        k_zpre<<<dim3(128, 6), 256>>>(w1, w2, encb);
        k_big<<<dim3(64, 3, 2), 256>>>(adjs);
        k_decode<<<512, 256>>>(dw, db, ow, ob, outp, p);
    }
}

// round 9
// speedup vs baseline: 6.2388x; 6.2388x over previous
#include <cuda_runtime.h>
#include <cuda_bf16.h>
#include <cstdint>
#include <cstddef>

#define N_NODES 4096
#define PSTEPS 10
#define NH (N_NODES*64)          /* 262144 */
#define NKI 32                   /* K iterations per CTA: 2048 / 64 */
#define STAGE_BYTES 24576        /* A 64x64 bf16 (8KB) + B 128x64 bf16 (16KB) */
#define DSM_BYTES (3*STAGE_BYTES + 1024)

// ---------------- device scratch (no allocation allowed) -------------------
__device__ float g_window[2*N_NODES*20];           // [B][N][T*D]
__device__ float g_pre[3*2*N_NODES*64];            // [E][B*N][H]
__device__ float g_part[12*NH];                    // [S=2][E=3][B=2][N][H]
__device__ float g_mask[N_NODES];
__device__ float g_cwAll[6*20*64];                 // combined conv@W weights
__device__ float g_bAll[6*64];                     // combined biases
__device__ __nv_bfloat16 g_Zt[3UL*128*4096];       // [E][b*64+h][m]  (B^T, k-contig)
__device__ __nv_bfloat16 g_adjbf[3UL*4096*4096];   // bf16 adjacency

// ---------------- helpers ---------------------------------------------------
__device__ __forceinline__ uint32_t smem_u32(const void* p) {
    uint32_t a;
    asm("{ .reg .u64 t; cvta.to.shared.u64 t, %1; cvt.u32.u64 %0, t; }" : "=r"(a) : "l"(p));
    return a;
}
__device__ __forceinline__ void ldm4(uint32_t& r0, uint32_t& r1, uint32_t& r2,
                                     uint32_t& r3, uint32_t a) {
    asm volatile("ldmatrix.sync.aligned.m8n8.x4.shared.b16 {%0,%1,%2,%3}, [%4];"
                 : "=r"(r0), "=r"(r1), "=r"(r2), "=r"(r3) : "r"(a));
}
__device__ __forceinline__ void mma16816(float* c, const uint32_t* a,
                                         uint32_t b0, uint32_t b1) {
    asm volatile(
        "mma.sync.aligned.m16n8k16.row.col.f32.bf16.bf16.f32 "
        "{%0,%1,%2,%3}, {%4,%5,%6,%7}, {%8,%9}, {%0,%1,%2,%3};"
        : "+f"(c[0]), "+f"(c[1]), "+f"(c[2]), "+f"(c[3])
        : "r"(a[0]), "r"(a[1]), "r"(a[2]), "r"(a[3]), "r"(b0), "r"(b1));
}

// ---------------- init kernels ---------------------------------------------
__global__ void k_init_window(const float* __restrict__ ts) {
    int idx = blockIdx.x * 256 + threadIdx.x;      // 163840 total
    int d = idx & 3;
    int r = idx >> 2;
    int t = r % 5;
    int bn = r / 5;
    int n = bn & (N_NODES - 1);
    int b = bn >> 12;
    g_window[idx] = ts[(((size_t)(b*5 + t))*N_NODES + n)*4 + d];
}

__global__ void k_mask(const float* __restrict__ adjs) {
    int m = blockIdx.x * 256 + threadIdx.x;
    float v = 0.f;
    for (size_t i = m; i < (size_t)3*N_NODES*N_NODES; i += N_NODES) {
        if (adjs[i] > 0.f) { v = 1.f; break; }
    }
    g_mask[m] = v;
}

// adjacency fp32 -> bf16 (once per launch)
__global__ void k_convA(const float* __restrict__ adjs) {
    size_t i = ((size_t)blockIdx.x * 256 + threadIdx.x) * 8;   // 24576 blocks
    float4 a = *(const float4*)(adjs + i);
    float4 b = *(const float4*)(adjs + i + 4);
    __nv_bfloat162 p0 = __floats2bfloat162_rn(a.x, a.y);
    __nv_bfloat162 p1 = __floats2bfloat162_rn(a.z, a.w);
    __nv_bfloat162 p2 = __floats2bfloat162_rn(b.x, b.y);
    __nv_bfloat162 p3 = __floats2bfloat162_rn(b.z, b.w);
    uint4 v;
    v.x = *(uint32_t*)&p0; v.y = *(uint32_t*)&p1;
    v.z = *(uint32_t*)&p2; v.w = *(uint32_t*)&p3;
    *(uint4*)(g_adjbf + i) = v;
}

// combined weights: CW[mt][td][h] = sum_f conv_w[td][f] * W[f][h]; biases too.
__global__ void k_prepw(const float* __restrict__ cw, const float* __restrict__ cb,
                        const float* __restrict__ w1, const float* __restrict__ w2,
                        const float* __restrict__ encb) {
    int mt = blockIdx.x;               // 0..5
    int e = (mt < 3) ? mt : mt - 3;
    const float* W = ((mt < 3) ? w1 : w2) + e*64*64;
    int h = threadIdx.x;               // 64 threads
    for (int td = 0; td < 20; td++) {
        float a = 0.f;
        for (int f = 0; f < 64; f++) a = fmaf(cw[td*64 + f], W[f*64 + h], a);
        g_cwAll[(mt*20 + td)*64 + h] = a;
    }
    float ba = 0.f;
    for (int f = 0; f < 64; f++) ba = fmaf(cb[f], W[f*64 + h], ba);
    if (mt >= 3) ba += encb[e*64 + h];
    g_bAll[mt*64 + h] = ba;
}

// ---------------- per-step: Zt (bf16, transposed) + pre (fp32) -------------
// Z_e = win @ CW1_e + zb_e ; pre_e = win @ CW2_e + pb_e     (K = 20)
__global__ __launch_bounds__(256) void k_zpre2() {
    __shared__ float sW[6*20*64];      // 30 KB
    __shared__ float sB[6*64];
    __shared__ float sWin[64][21];
    int tid = threadIdx.x;
    int g0 = blockIdx.x * 64;

    for (int q = tid; q < 6*20*64; q += 256) sW[q] = g_cwAll[q];
    for (int q = tid; q < 6*64;    q += 256) sB[q] = g_bAll[q];
    for (int q = tid; q < 64*20;   q += 256)
        sWin[q/20][q%20] = g_window[(size_t)(g0 + q/20)*20 + q%20];
    __syncthreads();

    int tx = tid & 15, ty = tid >> 4;
    int h0 = tx * 4;
    int b  = g0 >> 12;
    int m0 = (g0 & 4095) + ty*4;

#pragma unroll
    for (int mt = 0; mt < 6; mt++) {
        float acc[4][4];
#pragma unroll
        for (int i = 0; i < 4; i++)
#pragma unroll
            for (int j = 0; j < 4; j++) acc[i][j] = sB[mt*64 + h0 + j];
#pragma unroll
        for (int k = 0; k < 20; k++) {
            float4 w = *(float4*)&sW[(mt*20 + k)*64 + h0];
            float wv[4] = {w.x, w.y, w.z, w.w};
#pragma unroll
            for (int i = 0; i < 4; i++) {
                float a = sWin[ty*4 + i][k];
#pragma unroll
                for (int j = 0; j < 4; j++) acc[i][j] = fmaf(a, wv[j], acc[i][j]);
            }
        }
        if (mt < 3) {
#pragma unroll
            for (int j = 0; j < 4; j++) {
                __nv_bfloat162 p0 = __floats2bfloat162_rn(acc[0][j], acc[1][j]);
                __nv_bfloat162 p1 = __floats2bfloat162_rn(acc[2][j], acc[3][j]);
                uint2 v; v.x = *(uint32_t*)&p0; v.y = *(uint32_t*)&p1;
                *(uint2*)(g_Zt + (size_t)(mt*128 + b*64 + h0 + j)*4096 + m0) = v;
            }
        } else {
            int e = mt - 3;
#pragma unroll
            for (int i = 0; i < 4; i++)
                *(float4*)(g_pre + (size_t)e*(8192*64) + (size_t)(g0 + ty*4 + i)*64 + h0) =
                    make_float4(acc[i][0], acc[i][1], acc[i][2], acc[i][3]);
        }
    }
}

// ---------------- big GEMM on mma.sync (HMMA) -------------------------------
// part[s,e,b,n,h] = sum_{m in Kslice(s)} A_e[n,m] * Zt_e[b*64+h, m]
// CTA: 64 rows x 128 cols, 256 thr (8 warps, warp tile 32x32), KT=64, 3 stages.
// grid (64 row-tiles, E=3, S=2) = 384 CTAs.
__device__ __forceinline__ void issue_tile(uint32_t base, int st,
                                           const __nv_bfloat16* Ae,
                                           const __nv_bfloat16* Ze,
                                           int n0, int kk, int tid) {
    uint32_t sA = base + (uint32_t)st * STAGE_BYTES;
    uint32_t sB = sA + 8192;
#pragma unroll
    for (int k = 0; k < 2; k++) {                  // A: 64 rows x 8 chunks
        int q = tid + k*256;
        int r = q >> 3, c = q & 7;
        uint32_t off = (uint32_t)r*128 + (uint32_t)((c ^ (r & 7)) << 4);
        const void* g = Ae + (size_t)(n0 + r)*4096 + kk + c*8;
        asm volatile("cp.async.cg.shared.global [%0], [%1], 16;" :: "r"(sA + off), "l"(g));
    }
#pragma unroll
    for (int k = 0; k < 4; k++) {                  // B: 128 rows x 8 chunks
        int q = tid + k*256;
        int r = q >> 3, c = q & 7;
        uint32_t off = (uint32_t)r*128 + (uint32_t)((c ^ (r & 7)) << 4);
        const void* g = Ze + (size_t)r*4096 + kk + c*8;
        asm volatile("cp.async.cg.shared.global [%0], [%1], 16;" :: "r"(sB + off), "l"(g));
    }
    asm volatile("cp.async.commit_group;" ::: "memory");
}

__global__ __launch_bounds__(256, 2) void k_bigwmma() {
    extern __shared__ __align__(1024) char dsm[];
    const int tid = threadIdx.x;
    const int lane = tid & 31, wid = tid >> 5;
    const int wm = wid & 1, wn = wid >> 1;         // warp grid 2 x 4
    const int e = blockIdx.y, s = blockIdx.z;
    const int n0 = blockIdx.x * 64;
    const int k0 = s * 2048;
    uint32_t base = (smem_u32(dsm) + 1023u) & ~1023u;

    const __nv_bfloat16* Ae = g_adjbf + (size_t)e*4096*4096;
    const __nv_bfloat16* Ze = g_Zt    + (size_t)e*128*4096;

    // lane decomposition for ldmatrix addressing
    const int l7 = lane & 7;
    const int rA = wm*32 + l7 + ((lane >> 3) & 1)*8;   // + mi*16
    const int klA = lane >> 4;                          // k 16B-half
    const int rB = wn*32 + l7 + (lane >> 4)*8;          // + pair*16
    const int klB = (lane >> 3) & 1;

    float acc[2][4][4] = {};

    issue_tile(base, 0, Ae, Ze, n0, k0,      tid);
    issue_tile(base, 1, Ae, Ze, n0, k0 + 64, tid);

    for (int kt = 0; kt < NKI; kt++) {
        if (kt + 1 < NKI) asm volatile("cp.async.wait_group 1;" ::: "memory");
        else              asm volatile("cp.async.wait_group 0;" ::: "memory");
        __syncthreads();
        if (kt + 2 < NKI)
            issue_tile(base, (kt + 2) % 3, Ae, Ze, n0, k0 + (kt+2)*64, tid);

        uint32_t sA = base + (uint32_t)(kt % 3) * STAGE_BYTES;
        uint32_t sB = sA + 8192;
#pragma unroll
        for (int s4 = 0; s4 < 4; s4++) {
            uint32_t a[2][4], b[2][4];
#pragma unroll
            for (int mi = 0; mi < 2; mi++) {
                int r = rA + mi*16;
                uint32_t ad = sA + (uint32_t)r*128
                            + (uint32_t)((((2*s4 + klA) ^ (r & 7))) << 4);
                ldm4(a[mi][0], a[mi][1], a[mi][2], a[mi][3], ad);
            }
#pragma unroll
            for (int p = 0; p < 2; p++) {
                int r = rB + p*16;
                uint32_t bd = sB + (uint32_t)r*128
                            + (uint32_t)((((2*s4 + klB) ^ (r & 7))) << 4);
                ldm4(b[p][0], b[p][1], b[p][2], b[p][3], bd);
            }
#pragma unroll
            for (int mi = 0; mi < 2; mi++)
#pragma unroll
                for (int nj = 0; nj < 4; nj++) {
                    int p = nj >> 1, hf = nj & 1;
                    mma16816(acc[mi][nj], a[mi], b[p][hf*2], b[p][hf*2 + 1]);
                }
        }
        __syncthreads();
    }

    // epilogue: write fp32 partials
    const int g8 = lane >> 2, t2 = (lane & 3)*2;
#pragma unroll
    for (int mi = 0; mi < 2; mi++) {
#pragma unroll
        for (int nj = 0; nj < 4; nj++) {
            int c = wn*32 + nj*8 + t2;
            int b = c >> 6, h = c & 63;
            float* o = g_part + (size_t)(s*6 + e*2 + b)*NH;
            int row = n0 + wm*32 + mi*16 + g8;
            *(float2*)(o + (size_t)row*64 + h) =
                make_float2(acc[mi][nj][0], acc[mi][nj][1]);
            *(float2*)(o + (size_t)(row + 8)*64 + h) =
                make_float2(acc[mi][nj][2], acc[mi][nj][3]);
        }
    }
}

// ---------------- decode (cond fused in) -----------------------------------
__global__ __launch_bounds__(256) void k_decode(const float* __restrict__ dw,
                                                const float* __restrict__ db,
                                                const float* __restrict__ ow,
                                                const float* __restrict__ ob,
                                                const float* __restrict__ cw,
                                                const float* __restrict__ cb,
                                                float* __restrict__ outp, int step) {
    __shared__ float s_dw[64][132];   // transposed: [h][j], padded
    __shared__ float s_cw[20][64];
    __shared__ float s_ow[64][4];
    __shared__ float s_db[64], s_cb[64];
    __shared__ float s_ob[4];
    __shared__ float x[4][128];
    __shared__ float s_win[4][20];
    __shared__ float hv[4][64];
    __shared__ float nxt[4][4];
    int tid = threadIdx.x;

#pragma unroll
    for (int l = 0; l < 32; l++) {
        int q = tid + l*256;                 // dec_w linear: j*64 + h
        s_dw[q & 63][q >> 6] = dw[q];
    }
    for (int q = tid; q < 1280; q += 256) s_cw[q >> 6][q & 63] = cw[q];
    s_ow[tid >> 2][tid & 3] = ow[tid];       // out_w: 64x4
    if (tid < 64) { s_db[tid] = db[tid]; s_cb[tid] = cb[tid]; }
    if (tid < 4)  s_ob[tid] = ob[tid];
    __syncthreads();

    int ty = tid >> 6, tx = tid & 63;
    int bse = blockIdx.x * 16;
    for (int i = 0; i < 4; i++) {
        int g = bse + i*4 + ty;
        int b = g >> 12, n = g & (N_NODES - 1);

        if (tx < 20) s_win[ty][tx] = g_window[(size_t)g*20 + tx];
        __syncthreads();

        // cond = win . conv_w + conv_b   (K = 20)
        float cv = s_cb[tx];
#pragma unroll
        for (int k = 0; k < 20; k++) cv = fmaf(s_win[ty][k], s_cw[k][tx], cv);

        // encoded = tanh(sum_e tanh(part_s0 + part_s1 + pre)) * mask
        float ssum = 0.f;
#pragma unroll
        for (int e = 0; e < 3; e++) {
            size_t o0 = (size_t)(e*2 + b) * NH + (size_t)n*64 + tx;
            float pe = g_part[o0] + g_part[(size_t)6*NH + o0]
                     + g_pre[(size_t)e*(8192*64) + (size_t)g*64 + tx];
            ssum += tanhf(pe);
        }
        float enc = tanhf(ssum) * g_mask[n];
        x[ty][tx] = cv;
        x[ty][64 + tx] = enc;
        __syncthreads();

        // h = relu([cond, enc] @ dec_w + dec_b)
        float h = s_db[tx];
#pragma unroll
        for (int j = 0; j < 128; j += 4) {
            float4 xx = *(float4*)&x[ty][j];
            float4 ww = *(float4*)&s_dw[tx][j];
            h = fmaf(xx.x, ww.x, h); h = fmaf(xx.y, ww.y, h);
            h = fmaf(xx.z, ww.z, h); h = fmaf(xx.w, ww.w, h);
        }
        h = fmaxf(h, 0.f);
        hv[ty][tx] = h;
        __syncthreads();

        // nxt = win[t=4] + tanh(h @ out_w + out_b); shift window
        float wv = 0.f;
        if (tx < 16) wv = g_window[(size_t)g*20 + 4 + tx];
        if (tx < 4) {
            float o = s_ob[tx];
#pragma unroll
            for (int j = 0; j < 64; j++) o = fmaf(hv[ty][j], s_ow[j][tx], o);
            float nv = g_window[(size_t)g*20 + 16 + tx] + tanhf(o);
            nxt[ty][tx] = nv;
            outp[(((size_t)b*PSTEPS + step)*N_NODES + n)*4 + tx] = nv;
        }
        __syncthreads();
        if (tx < 16)      g_window[(size_t)g*20 + tx] = wv;
        else if (tx < 20) g_window[(size_t)g*20 + tx] = nxt[ty][tx - 16];
        __syncthreads();
    }
}

// ---------------------------------------------------------------------------
extern "C" void kernel_launch(void* const* d_in, const int* in_sizes, int n_in,
                              void* d_out, int out_size) {
    const float* ts   = (const float*)d_in[0];
    const float* adjs = (const float*)d_in[1];
    const float* cw   = (const float*)d_in[2];
    const float* cb   = (const float*)d_in[3];
    const float* w1   = (const float*)d_in[4];
    const float* w2   = (const float*)d_in[5];
    const float* encb = (const float*)d_in[6];
    const float* dw   = (const float*)d_in[7];
    const float* db   = (const float*)d_in[8];
    const float* ow   = (const float*)d_in[9];
    const float* ob   = (const float*)d_in[10];
    float* outp = (float*)d_out;

    cudaFuncSetAttribute(k_bigwmma, cudaFuncAttributeMaxDynamicSharedMemorySize, DSM_BYTES);

    k_init_window<<<640, 256>>>(ts);
    k_mask<<<16, 256>>>(adjs);
    k_convA<<<24576, 256>>>(adjs);
    k_prepw<<<6, 64>>>(cw, cb, w1, w2, encb);
    for (int p = 0; p < PSTEPS; p++) {
        k_zpre2<<<128, 256>>>();
        k_bigwmma<<<dim3(64, 3, 2), 256, DSM_BYTES>>>();
        k_decode<<<512, 256>>>(dw, db, ow, ob, cw, cb, outp, p);
    }
}

// round 10
// speedup vs baseline: 6.7046x; 1.0747x over previous
#include <cuda_runtime.h>
#include <cuda_bf16.h>
#include <cuda_fp8.h>
#include <cstdint>
#include <cstddef>

#define N_NODES 4096
#define PSTEPS 10
#define NH (N_NODES*64)          /* 262144 */
#define NKI 16                   /* K iterations per CTA: 2048 / 128 (fp8) */
#define STAGE_BYTES 24576        /* A 64x128B (8KB) + B 128x128B (16KB) */
#define DSM_BYTES (3*STAGE_BYTES + 1024)
#define ASCALE 4096.0f
#define INV_ASCALE (1.0f/4096.0f)

// ---------------- device scratch (no allocation allowed) -------------------
__device__ float g_window[2*N_NODES*20];           // [B][N][T*D]
__device__ float g_pre[3*2*N_NODES*64];            // [E][B*N][H]
__device__ float g_part[12*NH];                    // [S=2][E=3][B=2][N][H]
__device__ float g_mask[N_NODES];
__device__ float g_cwAll[6*20*64];                 // combined conv@W weights
__device__ float g_bAll[6*64];                     // combined biases
__device__ uint8_t g_Ztf8[3UL*128*4096];           // [E][b*64+h][m]  fp8 e4m3
__device__ uint8_t g_adjf8[3UL*4096*4096];         // fp8 e4m3 adjacency * 4096

// ---------------- helpers ---------------------------------------------------
__device__ __forceinline__ uint32_t smem_u32(const void* p) {
    uint32_t a;
    asm("{ .reg .u64 t; cvta.to.shared.u64 t, %1; cvt.u32.u64 %0, t; }" : "=r"(a) : "l"(p));
    return a;
}
__device__ __forceinline__ void ldm4(uint32_t& r0, uint32_t& r1, uint32_t& r2,
                                     uint32_t& r3, uint32_t a) {
    asm volatile("ldmatrix.sync.aligned.m8n8.x4.shared.b16 {%0,%1,%2,%3}, [%4];"
                 : "=r"(r0), "=r"(r1), "=r"(r2), "=r"(r3) : "r"(a));
}
// fp8 e4m3 MMA, k=32: byte-layout identical to the bf16 k=16 fragments.
__device__ __forceinline__ void mma16832f8(float* c, const uint32_t* a,
                                           uint32_t b0, uint32_t b1) {
    asm volatile(
        "mma.sync.aligned.m16n8k32.row.col.f32.e4m3.e4m3.f32 "
        "{%0,%1,%2,%3}, {%4,%5,%6,%7}, {%8,%9}, {%0,%1,%2,%3};"
        : "+f"(c[0]), "+f"(c[1]), "+f"(c[2]), "+f"(c[3])
        : "r"(a[0]), "r"(a[1]), "r"(a[2]), "r"(a[3]), "r"(b0), "r"(b1));
}

// ---------------- init kernels ---------------------------------------------
__global__ void k_init_window(const float* __restrict__ ts) {
    int idx = blockIdx.x * 256 + threadIdx.x;      // 163840 total
    int d = idx & 3;
    int r = idx >> 2;
    int t = r % 5;
    int bn = r / 5;
    int n = bn & (N_NODES - 1);
    int b = bn >> 12;
    g_window[idx] = ts[(((size_t)(b*5 + t))*N_NODES + n)*4 + d];
}

__global__ void k_mask(const float* __restrict__ adjs) {
    int m = blockIdx.x * 256 + threadIdx.x;
    float v = 0.f;
    for (size_t i = m; i < (size_t)3*N_NODES*N_NODES; i += N_NODES) {
        if (adjs[i] > 0.f) { v = 1.f; break; }
    }
    g_mask[m] = v;
}

// adjacency fp32 -> fp8 e4m3, scaled by 4096 (once per launch)
__global__ void k_convA(const float* __restrict__ adjs) {
    size_t i = ((size_t)blockIdx.x * 256 + threadIdx.x) * 8;   // 24576 blocks
    float4 a = *(const float4*)(adjs + i);
    float4 b = *(const float4*)(adjs + i + 4);
    __nv_fp8x4_e4m3 lo(make_float4(a.x*ASCALE, a.y*ASCALE, a.z*ASCALE, a.w*ASCALE));
    __nv_fp8x4_e4m3 hi(make_float4(b.x*ASCALE, b.y*ASCALE, b.z*ASCALE, b.w*ASCALE));
    uint2 v; v.x = lo.__x; v.y = hi.__x;
    *(uint2*)(g_adjf8 + i) = v;
}

// combined weights: CW[mt][td][h] = sum_f conv_w[td][f] * W[f][h]; biases too.
// grid (6, 21): y<20 -> one td row each; y==20 -> bias row. 64 threads = h.
__global__ void k_prepw(const float* __restrict__ cw, const float* __restrict__ cb,
                        const float* __restrict__ w1, const float* __restrict__ w2,
                        const float* __restrict__ encb) {
    int mt = blockIdx.x;
    int row = blockIdx.y;
    int e = (mt < 3) ? mt : mt - 3;
    const float* W = ((mt < 3) ? w1 : w2) + e*64*64;
    int h = threadIdx.x;
    const float* src = (row < 20) ? (cw + row*64) : cb;
    float a = 0.f;
#pragma unroll 8
    for (int f = 0; f < 64; f++) a = fmaf(src[f], W[f*64 + h], a);
    if (row < 20) {
        g_cwAll[(mt*20 + row)*64 + h] = a;
    } else {
        if (mt >= 3) a += encb[e*64 + h];
        g_bAll[mt*64 + h] = a;
    }
}

// ---------------- per-step: Zt (fp8, transposed) + pre (fp32) --------------
// Z_e = win @ CW1_e + zb_e ; pre_e = win @ CW2_e + pb_e     (K = 20)
__global__ __launch_bounds__(256) void k_zpre2() {
    __shared__ float sW[6*20*64];      // 30 KB
    __shared__ float sB[6*64];
    __shared__ float sWin[64][21];
    int tid = threadIdx.x;
    int g0 = blockIdx.x * 64;

    for (int q = tid; q < 6*20*64; q += 256) sW[q] = g_cwAll[q];
    for (int q = tid; q < 6*64;    q += 256) sB[q] = g_bAll[q];
    for (int q = tid; q < 64*20;   q += 256)
        sWin[q/20][q%20] = g_window[(size_t)(g0 + q/20)*20 + q%20];
    __syncthreads();

    int tx = tid & 15, ty = tid >> 4;
    int h0 = tx * 4;
    int b  = g0 >> 12;
    int m0 = (g0 & 4095) + ty*4;

#pragma unroll
    for (int mt = 0; mt < 6; mt++) {
        float acc[4][4];
#pragma unroll
        for (int i = 0; i < 4; i++)
#pragma unroll
            for (int j = 0; j < 4; j++) acc[i][j] = sB[mt*64 + h0 + j];
#pragma unroll
        for (int k = 0; k < 20; k++) {
            float4 w = *(float4*)&sW[(mt*20 + k)*64 + h0];
            float wv[4] = {w.x, w.y, w.z, w.w};
#pragma unroll
            for (int i = 0; i < 4; i++) {
                float a = sWin[ty*4 + i][k];
#pragma unroll
                for (int j = 0; j < 4; j++) acc[i][j] = fmaf(a, wv[j], acc[i][j]);
            }
        }
        if (mt < 3) {
#pragma unroll
            for (int j = 0; j < 4; j++) {
                // pack 4 consecutive m values (i=0..3) as fp8x4
                __nv_fp8x4_e4m3 p4(make_float4(acc[0][j], acc[1][j], acc[2][j], acc[3][j]));
                *(uint32_t*)(g_Ztf8 + (size_t)(mt*128 + b*64 + h0 + j)*4096 + m0) = p4.__x;
            }
        } else {
            int e = mt - 3;
#pragma unroll
            for (int i = 0; i < 4; i++)
                *(float4*)(g_pre + (size_t)e*(8192*64) + (size_t)(g0 + ty*4 + i)*64 + h0) =
                    make_float4(acc[i][0], acc[i][1], acc[i][2], acc[i][3]);
        }
    }
}

// ---------------- big GEMM on fp8 mma.sync ----------------------------------
// part[s,e,b,n,h] = sum_{m in Kslice(s)} A_e[n,m] * Zt_e[b*64+h, m] (x4096 scale)
// CTA: 64 rows x 128 cols, 256 thr (8 warps, warp tile 32x32), 128 k-bytes/stage.
// grid (64 row-tiles, E=3, S=2) = 384 CTAs.
__device__ __forceinline__ void issue_tile(uint32_t base, int st,
                                           const uint8_t* Ae,
                                           const uint8_t* Ze,
                                           int n0, int kk, int tid) {
    uint32_t sA = base + (uint32_t)st * STAGE_BYTES;
    uint32_t sB = sA + 8192;
#pragma unroll
    for (int k = 0; k < 2; k++) {                  // A: 64 rows x 8 x 16B
        int q = tid + k*256;
        int r = q >> 3, c = q & 7;
        uint32_t off = (uint32_t)r*128 + (uint32_t)((c ^ (r & 7)) << 4);
        const void* g = Ae + (size_t)(n0 + r)*4096 + kk + c*16;
        asm volatile("cp.async.cg.shared.global [%0], [%1], 16;" :: "r"(sA + off), "l"(g));
    }
#pragma unroll
    for (int k = 0; k < 4; k++) {                  // B: 128 rows x 8 x 16B
        int q = tid + k*256;
        int r = q >> 3, c = q & 7;
        uint32_t off = (uint32_t)r*128 + (uint32_t)((c ^ (r & 7)) << 4);
        const void* g = Ze + (size_t)r*4096 + kk + c*16;
        asm volatile("cp.async.cg.shared.global [%0], [%1], 16;" :: "r"(sB + off), "l"(g));
    }
    asm volatile("cp.async.commit_group;" ::: "memory");
}

__global__ __launch_bounds__(256, 2) void k_bigwmma() {
    extern __shared__ __align__(1024) char dsm[];
    const int tid = threadIdx.x;
    const int lane = tid & 31, wid = tid >> 5;
    const int wm = wid & 1, wn = wid >> 1;         // warp grid 2 x 4
    const int e = blockIdx.y, s = blockIdx.z;
    const int n0 = blockIdx.x * 64;
    const int k0 = s * 2048;                       // bytes == fp8 elements
    uint32_t base = (smem_u32(dsm) + 1023u) & ~1023u;

    const uint8_t* Ae = g_adjf8 + (size_t)e*4096*4096;
    const uint8_t* Ze = g_Ztf8  + (size_t)e*128*4096;

    // lane decomposition for ldmatrix addressing (byte-identical to bf16 k16)
    const int l7 = lane & 7;
    const int rA = wm*32 + l7 + ((lane >> 3) & 1)*8;   // + mi*16
    const int klA = lane >> 4;                          // 16B k-half
    const int rB = wn*32 + l7 + (lane >> 4)*8;          // + p*16
    const int klB = (lane >> 3) & 1;

    float acc[2][4][4] = {};

    issue_tile(base, 0, Ae, Ze, n0, k0,       tid);
    issue_tile(base, 1, Ae, Ze, n0, k0 + 128, tid);

    for (int kt = 0; kt < NKI; kt++) {
        if (kt + 1 < NKI) asm volatile("cp.async.wait_group 1;" ::: "memory");
        else              asm volatile("cp.async.wait_group 0;" ::: "memory");
        __syncthreads();
        if (kt + 2 < NKI)
            issue_tile(base, (kt + 2) % 3, Ae, Ze, n0, k0 + (kt+2)*128, tid);

        uint32_t sA = base + (uint32_t)(kt % 3) * STAGE_BYTES;
        uint32_t sB = sA + 8192;
#pragma unroll
        for (int s4 = 0; s4 < 4; s4++) {           // each s4 = 32 k-bytes = k32
            uint32_t a[2][4], b[2][4];
#pragma unroll
            for (int mi = 0; mi < 2; mi++) {
                int r = rA + mi*16;
                uint32_t ad = sA + (uint32_t)r*128
                            + (uint32_t)((((2*s4 + klA) ^ (r & 7))) << 4);
                ldm4(a[mi][0], a[mi][1], a[mi][2], a[mi][3], ad);
            }
#pragma unroll
            for (int p = 0; p < 2; p++) {
                int r = rB + p*16;
                uint32_t bd = sB + (uint32_t)r*128
                            + (uint32_t)((((2*s4 + klB) ^ (r & 7))) << 4);
                ldm4(b[p][0], b[p][1], b[p][2], b[p][3], bd);
            }
#pragma unroll
            for (int mi = 0; mi < 2; mi++)
#pragma unroll
                for (int nj = 0; nj < 4; nj++) {
                    int p = nj >> 1, hf = nj & 1;
                    mma16832f8(acc[mi][nj], a[mi], b[p][hf*2], b[p][hf*2 + 1]);
                }
        }
        __syncthreads();
    }

    // epilogue: write fp32 partials (still carrying the x4096 A-scale)
    const int g8 = lane >> 2, t2 = (lane & 3)*2;
#pragma unroll
    for (int mi = 0; mi < 2; mi++) {
#pragma unroll
        for (int nj = 0; nj < 4; nj++) {
            int c = wn*32 + nj*8 + t2;
            int b = c >> 6, h = c & 63;
            float* o = g_part + (size_t)(s*6 + e*2 + b)*NH;
            int row = n0 + wm*32 + mi*16 + g8;
            *(float2*)(o + (size_t)row*64 + h) =
                make_float2(acc[mi][nj][0], acc[mi][nj][1]);
            *(float2*)(o + (size_t)(row + 8)*64 + h) =
                make_float2(acc[mi][nj][2], acc[mi][nj][3]);
        }
    }
}

// ---------------- decode (cond fused in) -----------------------------------
__global__ __launch_bounds__(256) void k_decode(const float* __restrict__ dw,
                                                const float* __restrict__ db,
                                                const float* __restrict__ ow,
                                                const float* __restrict__ ob,
                                                const float* __restrict__ cw,
                                                const float* __restrict__ cb,
                                                float* __restrict__ outp, int step) {
    __shared__ float s_dw[64][132];   // transposed: [h][j], padded
    __shared__ float s_cw[20][64];
    __shared__ float s_ow[64][4];
    __shared__ float s_db[64], s_cb[64];
    __shared__ float s_ob[4];
    __shared__ float x[4][128];
    __shared__ float s_win[4][20];
    __shared__ float hv[4][64];
    __shared__ float nxt[4][4];
    int tid = threadIdx.x;

#pragma unroll
    for (int l = 0; l < 32; l++) {
        int q = tid + l*256;                 // dec_w linear: j*64 + h
        s_dw[q & 63][q >> 6] = dw[q];
    }
    for (int q = tid; q < 1280; q += 256) s_cw[q >> 6][q & 63] = cw[q];
    s_ow[tid >> 2][tid & 3] = ow[tid];       // out_w: 64x4
    if (tid < 64) { s_db[tid] = db[tid]; s_cb[tid] = cb[tid]; }
    if (tid < 4)  s_ob[tid] = ob[tid];
    __syncthreads();

    int ty = tid >> 6, tx = tid & 63;
    int bse = blockIdx.x * 16;
    for (int i = 0; i < 4; i++) {
        int g = bse + i*4 + ty;
        int b = g >> 12, n = g & (N_NODES - 1);

        if (tx < 20) s_win[ty][tx] = g_window[(size_t)g*20 + tx];
        __syncthreads();

        // cond = win . conv_w + conv_b   (K = 20)
        float cv = s_cb[tx];
#pragma unroll
        for (int k = 0; k < 20; k++) cv = fmaf(s_win[ty][k], s_cw[k][tx], cv);

        // encoded = tanh(sum_e tanh(part*(1/4096) + pre)) * mask
        float ssum = 0.f;
#pragma unroll
        for (int e = 0; e < 3; e++) {
            size_t o0 = (size_t)(e*2 + b) * NH + (size_t)n*64 + tx;
            float pe = (g_part[o0] + g_part[(size_t)6*NH + o0]) * INV_ASCALE
                     + g_pre[(size_t)e*(8192*64) + (size_t)g*64 + tx];
            ssum += tanhf(pe);
        }
        float enc = tanhf(ssum) * g_mask[n];
        x[ty][tx] = cv;
        x[ty][64 + tx] = enc;
        __syncthreads();

        // h = relu([cond, enc] @ dec_w + dec_b)
        float h = s_db[tx];
#pragma unroll
        for (int j = 0; j < 128; j += 4) {
            float4 xx = *(float4*)&x[ty][j];
            float4 ww = *(float4*)&s_dw[tx][j];
            h = fmaf(xx.x, ww.x, h); h = fmaf(xx.y, ww.y, h);
            h = fmaf(xx.z, ww.z, h); h = fmaf(xx.w, ww.w, h);
        }
        h = fmaxf(h, 0.f);
        hv[ty][tx] = h;
        __syncthreads();

        // nxt = win[t=4] + tanh(h @ out_w + out_b); shift window
        float wv = 0.f;
        if (tx < 16) wv = g_window[(size_t)g*20 + 4 + tx];
        if (tx < 4) {
            float o = s_ob[tx];
#pragma unroll
            for (int j = 0; j < 64; j++) o = fmaf(hv[ty][j], s_ow[j][tx], o);
            float nv = g_window[(size_t)g*20 + 16 + tx] + tanhf(o);
            nxt[ty][tx] = nv;
            outp[(((size_t)b*PSTEPS + step)*N_NODES + n)*4 + tx] = nv;
        }
        __syncthreads();
        if (tx < 16)      g_window[(size_t)g*20 + tx] = wv;
        else if (tx < 20) g_window[(size_t)g*20 + tx] = nxt[ty][tx - 16];
        __syncthreads();
    }
}

// ---------------------------------------------------------------------------
extern "C" void kernel_launch(void* const* d_in, const int* in_sizes, int n_in,
                              void* d_out, int out_size) {
    const float* ts   = (const float*)d_in[0];
    const float* adjs = (const float*)d_in[1];
    const float* cw   = (const float*)d_in[2];
    const float* cb   = (const float*)d_in[3];
    const float* w1   = (const float*)d_in[4];
    const float* w2   = (const float*)d_in[5];
    const float* encb = (const float*)d_in[6];
    const float* dw   = (const float*)d_in[7];
    const float* db   = (const float*)d_in[8];
    const float* ow   = (const float*)d_in[9];
    const float* ob   = (const float*)d_in[10];
    float* outp = (float*)d_out;

    cudaFuncSetAttribute(k_bigwmma, cudaFuncAttributeMaxDynamicSharedMemorySize, DSM_BYTES);

    k_init_window<<<640, 256>>>(ts);
    k_mask<<<16, 256>>>(adjs);
    k_convA<<<24576, 256>>>(adjs);
    k_prepw<<<dim3(6, 21), 64>>>(cw, cb, w1, w2, encb);
    for (int p = 0; p < PSTEPS; p++) {
        k_zpre2<<<128, 256>>>();
        k_bigwmma<<<dim3(64, 3, 2), 256, DSM_BYTES>>>();
        k_decode<<<512, 256>>>(dw, db, ow, ob, cw, cb, outp, p);
    }
}

// round 11
// speedup vs baseline: 6.9109x; 1.0308x over previous
#include <cuda_runtime.h>
#include <cuda_bf16.h>
#include <cuda_fp8.h>
#include <cstdint>
#include <cstddef>

#define N_NODES 4096
#define PSTEPS 10
#define NH (N_NODES*64)          /* 262144 */
#define NKI 16                   /* K iterations per CTA: 2048 / 128 (fp8) */
#define STAGE_BYTES 24576        /* A 64x128B (8KB) + B 128x128B (16KB) */
#define DSM_BYTES (3*STAGE_BYTES + 1024)
#define DEC_SMEM_FLOATS 15560
#define DEC_SMEM_BYTES (DEC_SMEM_FLOATS*4)
#define ASCALE 4096.0f
#define INV_ASCALE (1.0f/4096.0f)

// ---------------- device scratch (no allocation allowed) -------------------
__device__ float g_window[2*N_NODES*20];           // [B][N][T*D]
__device__ float g_pre[3*2*N_NODES*64];            // [E][B*N][H]
__device__ float g_part[12*NH];                    // [S=2][E=3][B=2][N][H]
__device__ float g_mask[N_NODES];
__device__ float g_cwAll[6*20*64];                 // combined conv@W weights
__device__ float g_bAll[6*64];                     // combined biases
__device__ uint8_t g_Ztf8[3UL*128*4096];           // [E][b*64+h][m]  fp8 e4m3
__device__ uint8_t g_adjf8[3UL*4096*4096];         // fp8 e4m3 adjacency * 4096

// ---------------- helpers ---------------------------------------------------
__device__ __forceinline__ uint32_t smem_u32(const void* p) {
    uint32_t a;
    asm("{ .reg .u64 t; cvta.to.shared.u64 t, %1; cvt.u32.u64 %0, t; }" : "=r"(a) : "l"(p));
    return a;
}
__device__ __forceinline__ void ldm4(uint32_t& r0, uint32_t& r1, uint32_t& r2,
                                     uint32_t& r3, uint32_t a) {
    asm volatile("ldmatrix.sync.aligned.m8n8.x4.shared.b16 {%0,%1,%2,%3}, [%4];"
                 : "=r"(r0), "=r"(r1), "=r"(r2), "=r"(r3) : "r"(a));
}
__device__ __forceinline__ void mma16832f8(float* c, const uint32_t* a,
                                           uint32_t b0, uint32_t b1) {
    asm volatile(
        "mma.sync.aligned.m16n8k32.row.col.f32.e4m3.e4m3.f32 "
        "{%0,%1,%2,%3}, {%4,%5,%6,%7}, {%8,%9}, {%0,%1,%2,%3};"
        : "+f"(c[0]), "+f"(c[1]), "+f"(c[2]), "+f"(c[3])
        : "r"(a[0]), "r"(a[1]), "r"(a[2]), "r"(a[3]), "r"(b0), "r"(b1));
}

// ---------------- init kernels ---------------------------------------------
__global__ void k_init_window(const float* __restrict__ ts) {
    int idx = blockIdx.x * 256 + threadIdx.x;      // 163840 total
    int d = idx & 3;
    int r = idx >> 2;
    int t = r % 5;
    int bn = r / 5;
    int n = bn & (N_NODES - 1);
    int b = bn >> 12;
    g_window[idx] = ts[(((size_t)(b*5 + t))*N_NODES + n)*4 + d];
}

__global__ void k_mask(const float* __restrict__ adjs) {
    int m = blockIdx.x * 256 + threadIdx.x;
    float v = 0.f;
    for (size_t i = m; i < (size_t)3*N_NODES*N_NODES; i += N_NODES) {
        if (adjs[i] > 0.f) { v = 1.f; break; }
    }
    g_mask[m] = v;
}

// adjacency fp32 -> fp8 e4m3, scaled by 4096 (once per launch)
__global__ void k_convA(const float* __restrict__ adjs) {
    size_t i = ((size_t)blockIdx.x * 256 + threadIdx.x) * 8;   // 24576 blocks
    float4 a = *(const float4*)(adjs + i);
    float4 b = *(const float4*)(adjs + i + 4);
    __nv_fp8x4_e4m3 lo(make_float4(a.x*ASCALE, a.y*ASCALE, a.z*ASCALE, a.w*ASCALE));
    __nv_fp8x4_e4m3 hi(make_float4(b.x*ASCALE, b.y*ASCALE, b.z*ASCALE, b.w*ASCALE));
    uint2 v; v.x = lo.__x; v.y = hi.__x;
    *(uint2*)(g_adjf8 + i) = v;
}

// combined weights: CW[mt][td][h] = sum_f conv_w[td][f] * W[f][h]; biases too.
__global__ void k_prepw(const float* __restrict__ cw, const float* __restrict__ cb,
                        const float* __restrict__ w1, const float* __restrict__ w2,
                        const float* __restrict__ encb) {
    int mt = blockIdx.x;
    int row = blockIdx.y;
    int e = (mt < 3) ? mt : mt - 3;
    const float* W = ((mt < 3) ? w1 : w2) + e*64*64;
    int h = threadIdx.x;
    const float* src = (row < 20) ? (cw + row*64) : cb;
    float a = 0.f;
#pragma unroll 8
    for (int f = 0; f < 64; f++) a = fmaf(src[f], W[f*64 + h], a);
    if (row < 20) {
        g_cwAll[(mt*20 + row)*64 + h] = a;
    } else {
        if (mt >= 3) a += encb[e*64 + h];
        g_bAll[mt*64 + h] = a;
    }
}

// ---------------- initial Zt/pre (step 0 only) ------------------------------
__global__ __launch_bounds__(256) void k_zpre2() {
    __shared__ float sW[6*20*64];
    __shared__ float sB[6*64];
    __shared__ float sWin[64][21];
    int tid = threadIdx.x;
    int g0 = blockIdx.x * 64;

    for (int q = tid; q < 6*20*64; q += 256) sW[q] = g_cwAll[q];
    for (int q = tid; q < 6*64;    q += 256) sB[q] = g_bAll[q];
    for (int q = tid; q < 64*20;   q += 256)
        sWin[q/20][q%20] = g_window[(size_t)(g0 + q/20)*20 + q%20];
    __syncthreads();

    int tx = tid & 15, ty = tid >> 4;
    int h0 = tx * 4;
    int b  = g0 >> 12;
    int m0 = (g0 & 4095) + ty*4;

#pragma unroll
    for (int mt = 0; mt < 6; mt++) {
        float acc[4][4];
#pragma unroll
        for (int i = 0; i < 4; i++)
#pragma unroll
            for (int j = 0; j < 4; j++) acc[i][j] = sB[mt*64 + h0 + j];
#pragma unroll
        for (int k = 0; k < 20; k++) {
            float4 w = *(float4*)&sW[(mt*20 + k)*64 + h0];
            float wv[4] = {w.x, w.y, w.z, w.w};
#pragma unroll
            for (int i = 0; i < 4; i++) {
                float a = sWin[ty*4 + i][k];
#pragma unroll
                for (int j = 0; j < 4; j++) acc[i][j] = fmaf(a, wv[j], acc[i][j]);
            }
        }
        if (mt < 3) {
#pragma unroll
            for (int j = 0; j < 4; j++) {
                __nv_fp8x4_e4m3 p4(make_float4(acc[0][j], acc[1][j], acc[2][j], acc[3][j]));
                *(uint32_t*)(g_Ztf8 + (size_t)(mt*128 + b*64 + h0 + j)*4096 + m0) = p4.__x;
            }
        } else {
            int e = mt - 3;
#pragma unroll
            for (int i = 0; i < 4; i++)
                *(float4*)(g_pre + (size_t)e*(8192*64) + (size_t)(g0 + ty*4 + i)*64 + h0) =
                    make_float4(acc[i][0], acc[i][1], acc[i][2], acc[i][3]);
        }
    }
}

// ---------------- big GEMM on fp8 mma.sync ----------------------------------
__device__ __forceinline__ void issue_tile(uint32_t base, int st,
                                           const uint8_t* Ae,
                                           const uint8_t* Ze,
                                           int n0, int kk, int tid) {
    uint32_t sA = base + (uint32_t)st * STAGE_BYTES;
    uint32_t sB = sA + 8192;
#pragma unroll
    for (int k = 0; k < 2; k++) {
        int q = tid + k*256;
        int r = q >> 3, c = q & 7;
        uint32_t off = (uint32_t)r*128 + (uint32_t)((c ^ (r & 7)) << 4);
        const void* g = Ae + (size_t)(n0 + r)*4096 + kk + c*16;
        asm volatile("cp.async.cg.shared.global [%0], [%1], 16;" :: "r"(sA + off), "l"(g));
    }
#pragma unroll
    for (int k = 0; k < 4; k++) {
        int q = tid + k*256;
        int r = q >> 3, c = q & 7;
        uint32_t off = (uint32_t)r*128 + (uint32_t)((c ^ (r & 7)) << 4);
        const void* g = Ze + (size_t)r*4096 + kk + c*16;
        asm volatile("cp.async.cg.shared.global [%0], [%1], 16;" :: "r"(sB + off), "l"(g));
    }
    asm volatile("cp.async.commit_group;" ::: "memory");
}

__global__ __launch_bounds__(256, 2) void k_bigwmma() {
    extern __shared__ __align__(1024) char dsm[];
    const int tid = threadIdx.x;
    const int lane = tid & 31, wid = tid >> 5;
    const int wm = wid & 1, wn = wid >> 1;
    const int e = blockIdx.y, s = blockIdx.z;
    const int n0 = blockIdx.x * 64;
    const int k0 = s * 2048;
    uint32_t base = (smem_u32(dsm) + 1023u) & ~1023u;

    const uint8_t* Ae = g_adjf8 + (size_t)e*4096*4096;
    const uint8_t* Ze = g_Ztf8  + (size_t)e*128*4096;

    const int l7 = lane & 7;
    const int rA = wm*32 + l7 + ((lane >> 3) & 1)*8;
    const int klA = lane >> 4;
    const int rB = wn*32 + l7 + (lane >> 4)*8;
    const int klB = (lane >> 3) & 1;

    float acc[2][4][4] = {};

    issue_tile(base, 0, Ae, Ze, n0, k0,       tid);
    issue_tile(base, 1, Ae, Ze, n0, k0 + 128, tid);

    for (int kt = 0; kt < NKI; kt++) {
        if (kt + 1 < NKI) asm volatile("cp.async.wait_group 1;" ::: "memory");
        else              asm volatile("cp.async.wait_group 0;" ::: "memory");
        __syncthreads();
        if (kt + 2 < NKI)
            issue_tile(base, (kt + 2) % 3, Ae, Ze, n0, k0 + (kt+2)*128, tid);

        uint32_t sA = base + (uint32_t)(kt % 3) * STAGE_BYTES;
        uint32_t sB = sA + 8192;
#pragma unroll
        for (int s4 = 0; s4 < 4; s4++) {
            uint32_t a[2][4], b[2][4];
#pragma unroll
            for (int mi = 0; mi < 2; mi++) {
                int r = rA + mi*16;
                uint32_t ad = sA + (uint32_t)r*128
                            + (uint32_t)((((2*s4 + klA) ^ (r & 7))) << 4);
                ldm4(a[mi][0], a[mi][1], a[mi][2], a[mi][3], ad);
            }
#pragma unroll
            for (int p = 0; p < 2; p++) {
                int r = rB + p*16;
                uint32_t bd = sB + (uint32_t)r*128
                            + (uint32_t)((((2*s4 + klB) ^ (r & 7))) << 4);
                ldm4(b[p][0], b[p][1], b[p][2], b[p][3], bd);
            }
#pragma unroll
            for (int mi = 0; mi < 2; mi++)
#pragma unroll
                for (int nj = 0; nj < 4; nj++) {
                    int p = nj >> 1, hf = nj & 1;
                    mma16832f8(acc[mi][nj], a[mi], b[p][hf*2], b[p][hf*2 + 1]);
                }
        }
        __syncthreads();
    }

    const int g8 = lane >> 2, t2 = (lane & 3)*2;
#pragma unroll
    for (int mi = 0; mi < 2; mi++) {
#pragma unroll
        for (int nj = 0; nj < 4; nj++) {
            int c = wn*32 + nj*8 + t2;
            int b = c >> 6, h = c & 63;
            float* o = g_part + (size_t)(s*6 + e*2 + b)*NH;
            int row = n0 + wm*32 + mi*16 + g8;
            *(float2*)(o + (size_t)row*64 + h) =
                make_float2(acc[mi][nj][0], acc[mi][nj][1]);
            *(float2*)(o + (size_t)(row + 8)*64 + h) =
                make_float2(acc[mi][nj][2], acc[mi][nj][3]);
        }
    }
}

// ---------------- fused decode + next-step Z/pre -----------------------------
// 512 thr = 16 warps = 16 nodes. Warp-per-node decode (no block syncs), then
// block-wide zpre for the same 16 nodes using the freshly shifted windows.
__global__ __launch_bounds__(512, 2) void k_decpre(const float* __restrict__ dw,
                                                   const float* __restrict__ db,
                                                   const float* __restrict__ ow,
                                                   const float* __restrict__ ob,
                                                   const float* __restrict__ cw,
                                                   const float* __restrict__ cb,
                                                   float* __restrict__ outp, int step) {
    extern __shared__ float sm[];
    float* s_dw  = sm;             // [64][132] transposed dec_w
    float* s_cw  = sm + 8448;      // [20][64]
    float* s_ow  = sm + 9728;      // [64][4]
    float* s_db  = sm + 9984;      // [64]
    float* s_cb  = sm + 10048;     // [64]
    float* s_ob  = sm + 10112;     // [4] (+pad)
    float* s_win = sm + 10120;     // [16][20]
    float* s_x   = sm + 10440;     // [16][128]
    float* s_pre = sm + 12488;     // [16][192]

    int tid = threadIdx.x;
    int g0 = blockIdx.x * 16;

    for (int q = tid; q < 8448; q += 512) s_dw[(q & 63)*132 + (q >> 6)] = dw[q];
    for (int q = tid; q < 1280; q += 512) s_cw[q] = cw[q];
    if (tid < 256) s_ow[tid] = ow[tid];
    else if (tid < 320) s_db[tid - 256] = db[tid - 256];
    else if (tid < 384) s_cb[tid - 320] = cb[tid - 320];
    else if (tid < 388) s_ob[tid - 384] = ob[tid - 384];
    for (int q = tid; q < 320; q += 512)
        s_win[q] = g_window[(size_t)(g0 + q/20)*20 + q%20];
    __syncthreads();

    const int w = tid >> 5, lane = tid & 31;
    const int g = g0 + w, b = g >> 12, n = g & 4095;
    const int c0 = lane, c1 = lane + 32;

    // ---- decode phase (warp-local) ----
    float cv0 = s_cb[c0], cv1 = s_cb[c1];
#pragma unroll
    for (int k = 0; k < 20; k++) {
        float wk = s_win[w*20 + k];
        cv0 = fmaf(wk, s_cw[k*64 + c0], cv0);
        cv1 = fmaf(wk, s_cw[k*64 + c1], cv1);
    }
    float ss0 = 0.f, ss1 = 0.f;
#pragma unroll
    for (int e = 0; e < 3; e++) {
        size_t o0 = (size_t)(e*2 + b)*NH + (size_t)n*64;
        const float* pr = g_pre + (size_t)e*(8192*64) + (size_t)g*64;
        float p0 = (g_part[o0 + c0] + g_part[(size_t)6*NH + o0 + c0]) * INV_ASCALE + pr[c0];
        float p1 = (g_part[o0 + c1] + g_part[(size_t)6*NH + o0 + c1]) * INV_ASCALE + pr[c1];
        ss0 += tanhf(p0); ss1 += tanhf(p1);
    }
    float mk = g_mask[n];
    s_x[w*128 + c0]      = cv0;
    s_x[w*128 + c1]      = cv1;
    s_x[w*128 + 64 + c0] = tanhf(ss0) * mk;
    s_x[w*128 + 96 + c0] = tanhf(ss1) * mk;
    __syncwarp();

    float h0 = s_db[c0], h1 = s_db[c1];
#pragma unroll
    for (int j = 0; j < 128; j += 4) {
        float4 xx = *(float4*)&s_x[w*128 + j];
        float4 w0 = *(float4*)&s_dw[c0*132 + j];
        float4 w1 = *(float4*)&s_dw[c1*132 + j];
        h0 = fmaf(xx.x, w0.x, h0); h0 = fmaf(xx.y, w0.y, h0);
        h0 = fmaf(xx.z, w0.z, h0); h0 = fmaf(xx.w, w0.w, h0);
        h1 = fmaf(xx.x, w1.x, h1); h1 = fmaf(xx.y, w1.y, h1);
        h1 = fmaf(xx.z, w1.z, h1); h1 = fmaf(xx.w, w1.w, h1);
    }
    h0 = fmaxf(h0, 0.f); h1 = fmaxf(h1, 0.f);

    float od[4];
#pragma unroll
    for (int d = 0; d < 4; d++)
        od[d] = h0*s_ow[c0*4 + d] + h1*s_ow[c1*4 + d];
#pragma unroll
    for (int off = 16; off; off >>= 1) {
#pragma unroll
        for (int d = 0; d < 4; d++)
            od[d] += __shfl_xor_sync(0xffffffffu, od[d], off);
    }
    float nvl = 0.f;
    if (lane < 4) nvl = s_win[w*20 + 16 + lane] + tanhf(od[lane] + s_ob[lane]);
    float old4 = (lane < 16) ? s_win[w*20 + lane + 4] : 0.f;
    float nvs  = __shfl_sync(0xffffffffu, nvl, lane & 3);
    float newv = (lane < 16) ? old4 : nvs;
    __syncwarp();
    if (lane < 20) {
        s_win[w*20 + lane] = newv;
        g_window[(size_t)g*20 + lane] = newv;
    }
    if (lane < 4)
        outp[(((size_t)b*PSTEPS + step)*4096 + n)*4 + lane] = nvl;
    __syncthreads();

    // ---- zpre phase: Zt/pre for next step, 16 nodes, new windows in s_win ----
    if (tid < 384) {
        int mt = tid >> 6, h = tid & 63;
        float acc[16];
        float bias = g_bAll[mt*64 + h];
#pragma unroll
        for (int i = 0; i < 16; i++) acc[i] = bias;
#pragma unroll
        for (int k = 0; k < 20; k++) {
            float wv = g_cwAll[(mt*20 + k)*64 + h];
#pragma unroll
            for (int i = 0; i < 16; i++)
                acc[i] = fmaf(s_win[i*20 + k], wv, acc[i]);
        }
        if (mt < 3) {
            int bb = g0 >> 12;
            __nv_fp8x4_e4m3 q0(make_float4(acc[0],  acc[1],  acc[2],  acc[3]));
            __nv_fp8x4_e4m3 q1(make_float4(acc[4],  acc[5],  acc[6],  acc[7]));
            __nv_fp8x4_e4m3 q2(make_float4(acc[8],  acc[9],  acc[10], acc[11]));
            __nv_fp8x4_e4m3 q3(make_float4(acc[12], acc[13], acc[14], acc[15]));
            uint4 v; v.x = q0.__x; v.y = q1.__x; v.z = q2.__x; v.w = q3.__x;
            *(uint4*)(g_Ztf8 + (size_t)(mt*128 + bb*64 + h)*4096 + (g0 & 4095)) = v;
        } else {
            int e = mt - 3;
#pragma unroll
            for (int i = 0; i < 16; i++)
                s_pre[i*192 + e*64 + h] = acc[i];
        }
    }
    __syncthreads();
    // coalesced pre writeback, warp-per-node
    for (int q = lane; q < 192; q += 32) {
        int e = q >> 6, hh = q & 63;
        g_pre[(size_t)e*(8192*64) + (size_t)g*64 + hh] = s_pre[w*192 + q];
    }
}

// ---------------------------------------------------------------------------
extern "C" void kernel_launch(void* const* d_in, const int* in_sizes, int n_in,
                              void* d_out, int out_size) {
    const float* ts   = (const float*)d_in[0];
    const float* adjs = (const float*)d_in[1];
    const float* cw   = (const float*)d_in[2];
    const float* cb   = (const float*)d_in[3];
    const float* w1   = (const float*)d_in[4];
    const float* w2   = (const float*)d_in[5];
    const float* encb = (const float*)d_in[6];
    const float* dw   = (const float*)d_in[7];
    const float* db   = (const float*)d_in[8];
    const float* ow   = (const float*)d_in[9];
    const float* ob   = (const float*)d_in[10];
    float* outp = (float*)d_out;

    cudaFuncSetAttribute(k_bigwmma, cudaFuncAttributeMaxDynamicSharedMemorySize, DSM_BYTES);
    cudaFuncSetAttribute(k_decpre,  cudaFuncAttributeMaxDynamicSharedMemorySize, DEC_SMEM_BYTES);

    k_init_window<<<640, 256>>>(ts);
    k_mask<<<16, 256>>>(adjs);
    k_convA<<<24576, 256>>>(adjs);
    k_prepw<<<dim3(6, 21), 64>>>(cw, cb, w1, w2, encb);
    k_zpre2<<<128, 256>>>();
    for (int p = 0; p < PSTEPS; p++) {
        k_bigwmma<<<dim3(64, 3, 2), 256, DSM_BYTES>>>();
        k_decpre<<<512, 512, DEC_SMEM_BYTES>>>(dw, db, ow, ob, cw, cb, outp, p);
    }
}